// round 3
// baseline (speedup 1.0000x reference)
#include <cuda_runtime.h>
#include <math.h>

#define QN 1000
#define KN 5
#define MN 50
#define DKN 64
#define DVN 128
#define DSN 50
#define BN 128
#define SN 2048

typedef unsigned long long ull;

// ---------- f32x2 helpers ----------
__device__ __forceinline__ ull ffma2(ull a, ull b, ull c) {
    ull d;
    asm("fma.rn.f32x2 %0, %1, %2, %3;" : "=l"(d) : "l"(a), "l"(b), "l"(c));
    return d;
}
__device__ __forceinline__ ull fadd2(ull a, ull b) {
    ull d;
    asm("add.rn.f32x2 %0, %1, %2;" : "=l"(d) : "l"(a), "l"(b));
    return d;
}
__device__ __forceinline__ ull fpack2(float lo, float hi) {
    ull r;
    asm("mov.b64 %0, {%1, %2};" : "=l"(r) : "f"(lo), "f"(hi));
    return r;
}
__device__ __forceinline__ float2 funpack2(ull v) {
    float2 f;
    asm("mov.b64 {%0, %1}, %2;" : "=f"(f.x), "=f"(f.y) : "l"(v));
    return f;
}

// ---------- scratch ----------
__device__ float g_attn[QN * MN];
__device__ float g_sq[QN * DSN];
__device__ float g_alphat[QN];
__device__ float g_betat[QN * (KN - 1)];
__device__ float g_erase[QN * KN * DVN];
__device__ float g_addt[QN * KN * DVN];
__device__ float g_reads[(size_t)BN * SN * DVN];

// ================= Kernel A: per-question tables =================
__global__ void k_qtab(const float* __restrict__ qe_w, const float* __restrict__ key_mem,
                       const float* __restrict__ sum_w, const float* __restrict__ sum_b,
                       const float* __restrict__ al_w, const float* __restrict__ al_b,
                       const float* __restrict__ be_w, const float* __restrict__ be_b) {
    int q = blockIdx.x, t = threadIdx.x;
    __shared__ float qe[DKN];
    __shared__ float sl[MN], se[MN];
    qe[t] = qe_w[q * DKN + t];
    __syncthreads();
    if (t < MN) {
        float acc = 0.f;
        #pragma unroll 8
        for (int k = 0; k < DKN; ++k) acc += qe[k] * key_mem[t * DKN + k];
        sl[t] = acc;
    }
    __syncthreads();
    if (t < MN) {
        float mx = -1e30f;
        for (int j = 0; j < MN; ++j) mx = fmaxf(mx, sl[j]);
        se[t] = expf(sl[t] - mx);
    }
    __syncthreads();
    if (t < MN) {
        float sm = 0.f;
        for (int j = 0; j < MN; ++j) sm += se[j];
        g_attn[q * MN + t] = se[t] / sm;
    }
    if (t < DSN) {
        float acc = sum_b[t];
        #pragma unroll 8
        for (int k = 0; k < DKN; ++k) acc += qe[k] * sum_w[(DVN + k) * DSN + t];
        g_sq[q * DSN + t] = acc;
    }
    if (t == 0) {
        float acc = al_b[0];
        for (int k = 0; k < DKN; ++k) acc += qe[k] * al_w[k];
        g_alphat[q] = fmaxf(acc, 0.f) + log1pf(expf(-fabsf(acc)));
    }
    if (t < KN - 1) {
        float acc = be_b[t];
        for (int k = 0; k < DKN; ++k) acc += qe[k] * be_w[k * (KN - 1) + t];
        g_betat[q * (KN - 1) + t] = acc;
    }
}

// ================= Kernel B: per-(q,r) erase/add tables =================
__global__ void k_vtab(const float* __restrict__ item_w,
                       const float* __restrict__ vp_w, const float* __restrict__ vp_b,
                       const float* __restrict__ er_w, const float* __restrict__ er_b,
                       const float* __restrict__ ad_w, const float* __restrict__ ad_b) {
    int c = blockIdx.x;
    int q = c / KN, r = c % KN;
    int t = threadIdx.x;
    __shared__ float item[DKN], rf[KN], ve[DVN];
    if (t < DKN) item[t] = item_w[q * DKN + t];
    if (t < KN)  rf[t] = fmaxf(1.f - fabsf((float)t - (float)r) * 0.25f, 0.f);
    __syncthreads();
    float acc = vp_b[t];
    #pragma unroll 8
    for (int k = 0; k < DKN; ++k) acc += item[k] * vp_w[k * DVN + t];
    #pragma unroll
    for (int j = 0; j < KN; ++j) acc += rf[j] * vp_w[(DKN + j) * DVN + t];
    ve[t] = acc;
    __syncthreads();
    float e = er_b[t], a = ad_b[t];
    #pragma unroll 8
    for (int k = 0; k < DVN; ++k) {
        float v = ve[k];
        e += v * er_w[k * DVN + t];
        a += v * ad_w[k * DVN + t];
    }
    g_erase[c * DVN + t] = 1.f / (1.f + expf(-e));
    g_addt[c * DVN + t]  = tanhf(a);
}

// ================= Kernel C: sequential scan (v3, m-pair packing) =================
// 128 CTAs, 256 threads = 8 warps. Warp wid owns v-columns [wid*16, wid*16+16).
// lane: vl = lane&15 -> v = wid*16+vl ; mh = lane>>4 (m-half).
// Each lane holds ONE v column over 26 m's as 13 f32x2 (m, m+1) pairs.
// Attention multiplier pairs load directly as LDS.64 (consecutive m).
// erase/add are per-v scalars, packed once per step. m-reduction: lane fold + shfl_xor(16).
#define ATT_PAD 52
#define SCAN_SMEM (QN * ATT_PAD * 4 + SN * 4 + SN)

__global__ void __launch_bounds__(256, 1)
k_scan(const int* __restrict__ questions, const int* __restrict__ responses,
       const float* __restrict__ init_mem) {
    extern __shared__ char smem_raw[];
    float* attn_sh = (float*)smem_raw;                 // QN*52 floats (8B-aligned rows)
    int*   q_sh    = (int*)(smem_raw + QN * ATT_PAD * 4);
    unsigned char* r_sh = (unsigned char*)(q_sh + SN);

    int b = blockIdx.x, tid = threadIdx.x;
    int wid  = tid >> 5;
    int lane = tid & 31;
    int vl   = lane & 15;
    int mh   = lane >> 4;
    int v    = wid * 16 + vl;
    int mstart = mh * 26;          // 26 m's per half (m 50,51 are zero-pad)

    for (int idx = tid; idx < QN * ATT_PAD; idx += 256) {
        int q = idx / ATT_PAD, m = idx - q * ATT_PAD;
        attn_sh[idx] = (m < MN) ? g_attn[q * MN + m] : 0.f;
    }
    for (int i = tid; i < SN; i += 256) {
        q_sh[i] = questions[b * SN + i];
        r_sh[i] = (unsigned char)responses[b * SN + i];
    }

    ull mem[13];
    #pragma unroll
    for (int i = 0; i < 13; ++i) {
        int m = mstart + 2 * i;
        float lo = (m     < MN) ? init_mem[m * DVN + v]       : 0.f;
        float hi = (m + 1 < MN) ? init_mem[(m + 1) * DVN + v] : 0.f;
        mem[i] = fpack2(lo, hi);
    }
    __syncthreads();

    // depth-2 prefetch of per-v erase/add scalars
    int c0 = q_sh[0] * KN + r_sh[0];
    int c1 = q_sh[1] * KN + r_sh[1];
    float e0  = g_erase[c0 * DVN + v];
    float ad0 = g_addt [c0 * DVN + v];
    float e1  = g_erase[c1 * DVN + v];
    float ad1 = g_addt [c1 * DVN + v];

    float* outp = g_reads + (size_t)b * SN * DVN + v;

    #pragma unroll 2
    for (int t = 0; t < SN; ++t) {
        float e_cur = e0, ad_cur = ad0;
        e0 = e1; ad0 = ad1;
        int tp = (t + 2 < SN) ? t + 2 : SN - 1;
        int cp = q_sh[tp] * KN + r_sh[tp];
        e1  = g_erase[cp * DVN + v];
        ad1 = g_addt [cp * DVN + v];

        float ne = -e_cur;
        ull neg_e2 = fpack2(ne, ne);
        ull ad2    = fpack2(ad_cur, ad_cur);
        const ull* ap_base = (const ull*)(attn_sh + q_sh[t] * ATT_PAD + mstart);

        ull r0 = 0ULL, r1 = 0ULL;
        #pragma unroll
        for (int i = 0; i < 13; ++i) {
            ull ap  = ap_base[i];                    // (a_m, a_m+1) broadcast LDS.64
            ull tmp = ffma2(neg_e2, mem[i], ad2);    // add - e*mem
            if (i & 1) r1 = ffma2(ap, mem[i], r1);
            else       r0 = ffma2(ap, mem[i], r0);
            mem[i] = ffma2(ap, tmp, mem[i]);         // mem += a*(add - e*mem)
        }
        float2 fr = funpack2(fadd2(r0, r1));
        float rv = fr.x + fr.y;                      // sum over this half's m
        rv += __shfl_xor_sync(0xffffffffu, rv, 16);  // other m-half
        if (mh == 0)
            outp[(size_t)t * DVN] = rv;
    }
}

// ================= Kernel D: epilogue (v3, 4-task register blocking) =================
// 256 threads, TILE_T=256 tasks. thread = (tg 0..63, jq 0..3); handles 4 tasks
// (tg + 64*i) x 7 output-pairs. reads tile staged coalesced; Ws in per-jq banks
// of 8 ull per v (16B aligned -> LDS.128 pairs).
#define TILE_T 256
#define R_STRIDE 132
#define EPI_SMEM (TILE_T * R_STRIDE * 4 + 4 * DVN * 8 * 8)

__global__ void __launch_bounds__(256, 1)
k_epi(const int* __restrict__ questions,
      const float* __restrict__ sum_w,
      const float* __restrict__ th_w, const float* __restrict__ th_b,
      float* __restrict__ out) {
    extern __shared__ char smem_raw[];
    float* tileR = (float*)smem_raw;
    ull*   Wsu   = (ull*)(smem_raw + TILE_T * R_STRIDE * 4);   // [jq][v][8]

    int tid = threadIdx.x;
    int t0 = blockIdx.x * TILE_T;

    // stage reads tile: coalesced float4
    for (int i = tid; i < TILE_T * (DVN / 4); i += 256) {
        int r = i >> 5, c4 = i & 31;
        float4 val = *(const float4*)(g_reads + (size_t)(t0 + r) * DVN + c4 * 4);
        *(float4*)(tileR + r * R_STRIDE + c4 * 4) = val;
    }
    // stage Ws into per-jq banks: Wsu[jq*1024 + v*8 + k] = (sum_w[v][2p], sum_w[v][2p+1]), p=jq*7+k
    for (int i = tid; i < 4 * DVN * 8; i += 256) {
        int jqi = i >> 10;
        int rem = i & 1023;
        int vv = rem >> 3, k = rem & 7;
        int p = jqi * 7 + k;
        ull val = 0ULL;
        if (k < 7 && p < 25)
            val = fpack2(sum_w[vv * DSN + 2 * p], sum_w[vv * DSN + 2 * p + 1]);
        Wsu[i] = val;
    }
    __syncthreads();

    int tg = tid >> 2;        // 0..63
    int jq = tid & 3;         // 0..3
    const ull* wq = Wsu + jq * (DVN * 8);

    ull acc[4][7];
    #pragma unroll
    for (int i = 0; i < 4; ++i)
        #pragma unroll
        for (int k = 0; k < 7; ++k) acc[i][k] = 0ULL;

    #pragma unroll 2
    for (int vv = 0; vv < DVN; vv += 2) {
        float2 rr[4];
        #pragma unroll
        for (int i = 0; i < 4; ++i)
            rr[i] = *(const float2*)(tileR + (tg + 64 * i) * R_STRIDE + vv);
        #pragma unroll
        for (int s = 0; s < 2; ++s) {
            const ull* w = wq + (vv + s) * 8;
            ull rp[4];
            #pragma unroll
            for (int i = 0; i < 4; ++i) {
                float x = s ? rr[i].y : rr[i].x;
                rp[i] = fpack2(x, x);
            }
            #pragma unroll
            for (int k = 0; k < 7; ++k) {
                ull wv = w[k];
                #pragma unroll
                for (int i = 0; i < 4; ++i)
                    acc[i][k] = ffma2(rp[i], wv, acc[i][k]);
            }
        }
    }

    float thb = th_b[0];
    const int N = BN * SN;

    #pragma unroll
    for (int i = 0; i < 4; ++i) {
        int task = t0 + tg + 64 * i;
        int qid = questions[task];
        float thp = 0.f;
        #pragma unroll
        for (int k = 0; k < 7; ++k) {
            int p = jq * 7 + k;
            if (p < 25) {
                float2 ac = funpack2(acc[i][k]);
                float2 sq2 = funpack2(*(const ull*)(g_sq + qid * DSN + 2 * p));
                float2 tw  = funpack2(*(const ull*)(th_w + 2 * p));
                float s0 = tanhf(ac.x + sq2.x);
                float s1 = tanhf(ac.y + sq2.y);
                thp += s0 * tw.x + s1 * tw.y;
            }
        }
        thp += __shfl_xor_sync(0xffffffffu, thp, 1);
        thp += __shfl_xor_sync(0xffffffffu, thp, 2);
        if (jq == 0) {
            float theta = tanhf(thp + thb);
            float alpha = g_alphat[qid];
            float inter = theta * alpha;
            float b0 = g_betat[qid * 4 + 0];
            float b1 = g_betat[qid * 4 + 1];
            float b2 = g_betat[qid * 4 + 2];
            float b3 = g_betat[qid * 4 + 3];
            float l0 = 0.f;
            float l1 = inter - b0;
            float l2 = l1 + inter - b1;
            float l3 = l2 + inter - b2;
            float l4 = l3 + inter - b3;
            float mx = fmaxf(fmaxf(fmaxf(l0, l1), fmaxf(l2, l3)), l4);
            float e0x = expf(l0 - mx), e1x = expf(l1 - mx), e2x = expf(l2 - mx);
            float e3x = expf(l3 - mx), e4x = expf(l4 - mx);
            float inv = 1.f / (e0x + e1x + e2x + e3x + e4x);

            out[task] = theta;
            out[N + task] = alpha;
            float* bo = out + 2 * N + (size_t)task * 4;
            bo[0] = b0; bo[1] = b1; bo[2] = b2; bo[3] = b3;
            float* lo = out + 6 * N + (size_t)task * 5;
            lo[0] = l0; lo[1] = l1; lo[2] = l2; lo[3] = l3; lo[4] = l4;
            float* po = out + 11 * N + (size_t)task * 5;
            po[0] = e0x * inv; po[1] = e1x * inv; po[2] = e2x * inv;
            po[3] = e3x * inv; po[4] = e4x * inv;
        }
    }
}

// ================= launch =================
extern "C" void kernel_launch(void* const* d_in, const int* in_sizes, int n_in,
                              void* d_out, int out_size) {
    const int*   questions  = (const int*)d_in[0];
    const int*   responses  = (const int*)d_in[1];
    const float* q_embed_w  = (const float*)d_in[2];
    const float* item_w     = (const float*)d_in[3];
    const float* vp_w       = (const float*)d_in[4];
    const float* vp_b       = (const float*)d_in[5];
    const float* key_mem    = (const float*)d_in[6];
    const float* init_mem   = (const float*)d_in[7];
    const float* er_w       = (const float*)d_in[8];
    const float* er_b       = (const float*)d_in[9];
    const float* ad_w       = (const float*)d_in[10];
    const float* ad_b       = (const float*)d_in[11];
    const float* sum_w      = (const float*)d_in[12];
    const float* sum_b      = (const float*)d_in[13];
    const float* th_w       = (const float*)d_in[14];
    const float* th_b       = (const float*)d_in[15];
    const float* al_w       = (const float*)d_in[16];
    const float* al_b       = (const float*)d_in[17];
    const float* be_w       = (const float*)d_in[18];
    const float* be_b       = (const float*)d_in[19];
    float* out = (float*)d_out;

    static int configured = 0;
    if (!configured) {
        cudaFuncSetAttribute(k_scan, cudaFuncAttributeMaxDynamicSharedMemorySize, SCAN_SMEM);
        cudaFuncSetAttribute(k_epi,  cudaFuncAttributeMaxDynamicSharedMemorySize, EPI_SMEM);
        configured = 1;
    }

    k_qtab<<<QN, 64>>>(q_embed_w, key_mem, sum_w, sum_b, al_w, al_b, be_w, be_b);
    k_vtab<<<QN * KN, DVN>>>(item_w, vp_w, vp_b, er_w, er_b, ad_w, ad_b);
    k_scan<<<BN, 256, SCAN_SMEM>>>(questions, responses, init_mem);
    k_epi<<<(BN * SN) / TILE_T, 256, EPI_SMEM>>>(questions, sum_w, th_w, th_b, out);
}

// round 4
// speedup vs baseline: 1.5220x; 1.5220x over previous
#include <cuda_runtime.h>
#include <math.h>

#define QN 1000
#define KN 5
#define MN 50
#define DKN 64
#define DVN 128
#define DSN 50
#define BN 128
#define SN 2048

typedef unsigned long long ull;

// ---------- f32x2 helpers ----------
__device__ __forceinline__ ull ffma2(ull a, ull b, ull c) {
    ull d;
    asm("fma.rn.f32x2 %0, %1, %2, %3;" : "=l"(d) : "l"(a), "l"(b), "l"(c));
    return d;
}
__device__ __forceinline__ ull fpack2(float lo, float hi) {
    ull r;
    asm("mov.b64 %0, {%1, %2};" : "=l"(r) : "f"(lo), "f"(hi));
    return r;
}
__device__ __forceinline__ float2 funpack2(ull v) {
    float2 f;
    asm("mov.b64 {%0, %1}, %2;" : "=f"(f.x), "=f"(f.y) : "l"(v));
    return f;
}

// ---------- scratch ----------
__device__ float g_attn[QN * MN];
__device__ float g_sq[QN * DSN];
__device__ float g_alphat[QN];
__device__ float g_betat[QN * (KN - 1)];
__device__ float g_erase[QN * KN * DVN];
__device__ float g_addt[QN * KN * DVN];
__device__ float g_reads[(size_t)BN * SN * DVN];

// ================= Kernel A: per-question tables =================
__global__ void k_qtab(const float* __restrict__ qe_w, const float* __restrict__ key_mem,
                       const float* __restrict__ sum_w, const float* __restrict__ sum_b,
                       const float* __restrict__ al_w, const float* __restrict__ al_b,
                       const float* __restrict__ be_w, const float* __restrict__ be_b) {
    int q = blockIdx.x, t = threadIdx.x;
    __shared__ float qe[DKN];
    __shared__ float sl[MN], se[MN];
    qe[t] = qe_w[q * DKN + t];
    __syncthreads();
    if (t < MN) {
        float acc = 0.f;
        #pragma unroll 8
        for (int k = 0; k < DKN; ++k) acc += qe[k] * key_mem[t * DKN + k];
        sl[t] = acc;
    }
    __syncthreads();
    if (t < MN) {
        float mx = -1e30f;
        for (int j = 0; j < MN; ++j) mx = fmaxf(mx, sl[j]);
        se[t] = expf(sl[t] - mx);
    }
    __syncthreads();
    if (t < MN) {
        float sm = 0.f;
        for (int j = 0; j < MN; ++j) sm += se[j];
        g_attn[q * MN + t] = se[t] / sm;
    }
    if (t < DSN) {
        float acc = sum_b[t];
        #pragma unroll 8
        for (int k = 0; k < DKN; ++k) acc += qe[k] * sum_w[(DVN + k) * DSN + t];
        g_sq[q * DSN + t] = acc;
    }
    if (t == 0) {
        float acc = al_b[0];
        for (int k = 0; k < DKN; ++k) acc += qe[k] * al_w[k];
        g_alphat[q] = fmaxf(acc, 0.f) + log1pf(expf(-fabsf(acc)));
    }
    if (t < KN - 1) {
        float acc = be_b[t];
        for (int k = 0; k < DKN; ++k) acc += qe[k] * be_w[k * (KN - 1) + t];
        g_betat[q * (KN - 1) + t] = acc;
    }
}

// ================= Kernel B: per-(q,r) erase/add tables =================
__global__ void k_vtab(const float* __restrict__ item_w,
                       const float* __restrict__ vp_w, const float* __restrict__ vp_b,
                       const float* __restrict__ er_w, const float* __restrict__ er_b,
                       const float* __restrict__ ad_w, const float* __restrict__ ad_b) {
    int c = blockIdx.x;
    int q = c / KN, r = c % KN;
    int t = threadIdx.x;
    __shared__ float item[DKN], rf[KN], ve[DVN];
    if (t < DKN) item[t] = item_w[q * DKN + t];
    if (t < KN)  rf[t] = fmaxf(1.f - fabsf((float)t - (float)r) * 0.25f, 0.f);
    __syncthreads();
    float acc = vp_b[t];
    #pragma unroll 8
    for (int k = 0; k < DKN; ++k) acc += item[k] * vp_w[k * DVN + t];
    #pragma unroll
    for (int j = 0; j < KN; ++j) acc += rf[j] * vp_w[(DKN + j) * DVN + t];
    ve[t] = acc;
    __syncthreads();
    float e = er_b[t], a = ad_b[t];
    #pragma unroll 8
    for (int k = 0; k < DVN; ++k) {
        float v = ve[k];
        e += v * er_w[k * DVN + t];
        a += v * ad_w[k * DVN + t];
    }
    g_erase[c * DVN + t] = 1.f / (1.f + expf(-e));
    g_addt[c * DVN + t]  = tanhf(a);
}

// ================= Kernel C: sequential scan (v4: v2 orientation, 512 threads) =================
// 128 CTAs, 512 threads = 16 warps (4 per SMSP for latency hiding).
// Warp wid owns 4 v-pairs: vp = wid*4 + (lane&3). mg = lane>>2: 8 m-groups of 7
// (m = mg*7 + i; m 50..55 are zero-pad). Per-thread state: 7 f32x2 (v-pair, m scalar).
// q/r prefetched depth-3 in registers; erase/add rows depth-2. Attention table
// (padded to 56 cols) fills dynamic smem. Reduction over mg: shfl_xor 4/8/16.
#define ATT_PAD 56
#define SCAN_SMEM (QN * ATT_PAD * 4)

__global__ void __launch_bounds__(512, 1)
k_scan(const int* __restrict__ questions, const int* __restrict__ responses,
       const float* __restrict__ init_mem) {
    extern __shared__ float attn_sh[];                 // QN*56 floats

    int b = blockIdx.x, tid = threadIdx.x;
    int wid  = tid >> 5;
    int lane = tid & 31;
    int vsub = lane & 3;
    int mg   = lane >> 2;
    int vp   = wid * 4 + vsub;        // v-pair: v = 2vp, 2vp+1
    int mstart = mg * 7;

    for (int idx = tid; idx < QN * ATT_PAD; idx += 512) {
        int q = idx / ATT_PAD, m = idx - q * ATT_PAD;
        attn_sh[idx] = (m < MN) ? g_attn[q * MN + m] : 0.f;
    }

    ull mem[7];
    #pragma unroll
    for (int i = 0; i < 7; ++i) {
        int m = mstart + i;
        mem[i] = (m < MN) ? *(const ull*)(init_mem + m * DVN + 2 * vp) : 0ULL;
    }
    __syncthreads();

    const int* qb = questions + b * SN;
    const int* rb = responses + b * SN;

    // register pipelines: q/r depth-3, e/ad depth-2
    int qa = qb[0], ra = rb[0];
    int qn1 = qb[1], rn1 = rb[1];
    int qn2 = qb[2], rn2 = rb[2];
    int ca = qa * KN + ra;
    int cb = qn1 * KN + rn1;
    ull e0  = *(const ull*)(g_erase + ca * DVN + 2 * vp);
    ull ad0 = *(const ull*)(g_addt  + ca * DVN + 2 * vp);
    ull e1  = *(const ull*)(g_erase + cb * DVN + 2 * vp);
    ull ad1 = *(const ull*)(g_addt  + cb * DVN + 2 * vp);

    const float* abase = attn_sh + mstart;
    float* outp = g_reads + (size_t)b * SN * DVN + 2 * vp;

    #pragma unroll 2
    for (int t = 0; t < SN; ++t) {
        int q_cur = qa;
        ull e_cur = e0, ad_cur = ad0;

        // issue prefetches: e/ad for t+2 (from already-arrived q/r), q/r for t+3
        int cc = qn2 * KN + rn2;
        ull e2  = *(const ull*)(g_erase + cc * DVN + 2 * vp);
        ull ad2 = *(const ull*)(g_addt  + cc * DVN + 2 * vp);
        int tn = (t + 3 < SN) ? t + 3 : SN - 1;
        int qn3 = qb[tn], rn3 = rb[tn];

        ull neg_e = e_cur ^ 0x8000000080000000ULL;
        const float* ab = abase + q_cur * ATT_PAD;
        ull r0 = 0ULL, r1 = 0ULL;
        #pragma unroll
        for (int i = 0; i < 7; ++i) {
            float a = ab[i];                         // broadcast LDS (0 for pad m)
            ull ap = fpack2(a, a);
            ull tmp = ffma2(neg_e, mem[i], ad_cur);  // add - e*mem
            if (i & 1) r1 = ffma2(ap, mem[i], r1);
            else       r0 = ffma2(ap, mem[i], r0);
            mem[i] = ffma2(ap, tmp, mem[i]);         // mem += a*(add - e*mem)
        }
        float2 fa = funpack2(r0), fb = funpack2(r1);
        float rx = fa.x + fb.x, ry = fa.y + fb.y;
        rx += __shfl_xor_sync(0xffffffffu, rx, 4);
        ry += __shfl_xor_sync(0xffffffffu, ry, 4);
        rx += __shfl_xor_sync(0xffffffffu, rx, 8);
        ry += __shfl_xor_sync(0xffffffffu, ry, 8);
        rx += __shfl_xor_sync(0xffffffffu, rx, 16);
        ry += __shfl_xor_sync(0xffffffffu, ry, 16);
        if (mg == 0)
            *(float2*)(outp + (size_t)t * DVN) = make_float2(rx, ry);

        // rotate pipelines
        qa = qn1; ra = rn1; qn1 = qn2; rn1 = rn2; qn2 = qn3; rn2 = rn3;
        e0 = e1; ad0 = ad1; e1 = e2; ad1 = ad2;
    }
}

// ================= Kernel D: epilogue (v4: v2 + conflict-free aligned W banks) =================
// 256 threads, TILE_T=128 tasks, 2 tasks/thread (tg, tg+64) x 7 output-pairs (jq).
// Weight banks: per-jq, stride 1028 ull (8224 B -> word-bank offset 8 per jq: conflict-free),
// rows of 8 ull (64 B, 16B-aligned -> LDS.128x3 + LDS.64).
#define TILE_T 128
#define R_STRIDE 132
#define WB_STRIDE 1028
#define EPI_SMEM (TILE_T * R_STRIDE * 4 + 4 * WB_STRIDE * 8)

__global__ void __launch_bounds__(256, 2)
k_epi(const int* __restrict__ questions,
      const float* __restrict__ sum_w,
      const float* __restrict__ th_w, const float* __restrict__ th_b,
      float* __restrict__ out) {
    extern __shared__ char smem_raw[];
    float* tileR = (float*)smem_raw;
    ull*   Wsu   = (ull*)(smem_raw + TILE_T * R_STRIDE * 4);   // [jq][v][8] stride 1028

    int tid = threadIdx.x;
    int t0 = blockIdx.x * TILE_T;

    // stage reads tile: coalesced float4
    for (int i = tid; i < TILE_T * (DVN / 4); i += 256) {
        int r = i >> 5, c4 = i & 31;
        float4 val = *(const float4*)(g_reads + (size_t)(t0 + r) * DVN + c4 * 4);
        *(float4*)(tileR + r * R_STRIDE + c4 * 4) = val;
    }
    // stage W banks: Wsu[jq*1028 + v*8 + k] = (sum_w[v][2p], sum_w[v][2p+1]), p = jq*7+k
    for (int i = tid; i < 4 * DVN * 8; i += 256) {
        int jqi = i >> 10;
        int rem = i & 1023;
        int vv = rem >> 3, k = rem & 7;
        int p = jqi * 7 + k;
        ull val = 0ULL;
        if (k < 7 && p < 25)
            val = fpack2(sum_w[vv * DSN + 2 * p], sum_w[vv * DSN + 2 * p + 1]);
        Wsu[jqi * WB_STRIDE + rem] = val;
    }
    __syncthreads();

    int tg = tid >> 2;        // 0..63
    int jq = tid & 3;         // 0..3
    const float* rrow0 = tileR + tg * R_STRIDE;
    const float* rrow1 = tileR + (tg + 64) * R_STRIDE;
    const ull* wq = Wsu + jq * WB_STRIDE;

    ull acc0[7], acc1[7];
    #pragma unroll
    for (int k = 0; k < 7; ++k) { acc0[k] = 0ULL; acc1[k] = 0ULL; }

    #pragma unroll 2
    for (int vv = 0; vv < DVN; vv += 2) {
        float2 ra = *(const float2*)(rrow0 + vv);
        float2 rb = *(const float2*)(rrow1 + vv);
        #pragma unroll
        for (int s = 0; s < 2; ++s) {
            const ull* w = wq + (vv + s) * 8;
            float xa = s ? ra.y : ra.x;
            float xb = s ? rb.y : rb.x;
            ull rp0 = fpack2(xa, xa);
            ull rp1 = fpack2(xb, xb);
            #pragma unroll
            for (int k = 0; k < 7; ++k) {
                ull wv = w[k];
                acc0[k] = ffma2(rp0, wv, acc0[k]);
                acc1[k] = ffma2(rp1, wv, acc1[k]);
            }
        }
    }

    float thb = th_b[0];
    const int N = BN * SN;

    #pragma unroll
    for (int i = 0; i < 2; ++i) {
        int task = t0 + tg + 64 * i;
        ull* acc = i ? acc1 : acc0;
        int qid = questions[task];
        float thp = 0.f;
        #pragma unroll
        for (int k = 0; k < 7; ++k) {
            int p = jq * 7 + k;
            if (p < 25) {
                float2 ac = funpack2(acc[k]);
                float2 sq2 = funpack2(*(const ull*)(g_sq + qid * DSN + 2 * p));
                float2 tw  = funpack2(*(const ull*)(th_w + 2 * p));
                float s0 = tanhf(ac.x + sq2.x);
                float s1 = tanhf(ac.y + sq2.y);
                thp += s0 * tw.x + s1 * tw.y;
            }
        }
        thp += __shfl_xor_sync(0xffffffffu, thp, 1);
        thp += __shfl_xor_sync(0xffffffffu, thp, 2);
        if (jq == 0) {
            float theta = tanhf(thp + thb);
            float alpha = g_alphat[qid];
            float inter = theta * alpha;
            float b0 = g_betat[qid * 4 + 0];
            float b1 = g_betat[qid * 4 + 1];
            float b2 = g_betat[qid * 4 + 2];
            float b3 = g_betat[qid * 4 + 3];
            float l0 = 0.f;
            float l1 = inter - b0;
            float l2 = l1 + inter - b1;
            float l3 = l2 + inter - b2;
            float l4 = l3 + inter - b3;
            float mx = fmaxf(fmaxf(fmaxf(l0, l1), fmaxf(l2, l3)), l4);
            float e0x = expf(l0 - mx), e1x = expf(l1 - mx), e2x = expf(l2 - mx);
            float e3x = expf(l3 - mx), e4x = expf(l4 - mx);
            float inv = 1.f / (e0x + e1x + e2x + e3x + e4x);

            out[task] = theta;
            out[N + task] = alpha;
            float* bo = out + 2 * N + (size_t)task * 4;
            bo[0] = b0; bo[1] = b1; bo[2] = b2; bo[3] = b3;
            float* lo = out + 6 * N + (size_t)task * 5;
            lo[0] = l0; lo[1] = l1; lo[2] = l2; lo[3] = l3; lo[4] = l4;
            float* po = out + 11 * N + (size_t)task * 5;
            po[0] = e0x * inv; po[1] = e1x * inv; po[2] = e2x * inv;
            po[3] = e3x * inv; po[4] = e4x * inv;
        }
    }
}

// ================= launch =================
extern "C" void kernel_launch(void* const* d_in, const int* in_sizes, int n_in,
                              void* d_out, int out_size) {
    const int*   questions  = (const int*)d_in[0];
    const int*   responses  = (const int*)d_in[1];
    const float* q_embed_w  = (const float*)d_in[2];
    const float* item_w     = (const float*)d_in[3];
    const float* vp_w       = (const float*)d_in[4];
    const float* vp_b       = (const float*)d_in[5];
    const float* key_mem    = (const float*)d_in[6];
    const float* init_mem   = (const float*)d_in[7];
    const float* er_w       = (const float*)d_in[8];
    const float* er_b       = (const float*)d_in[9];
    const float* ad_w       = (const float*)d_in[10];
    const float* ad_b       = (const float*)d_in[11];
    const float* sum_w      = (const float*)d_in[12];
    const float* sum_b      = (const float*)d_in[13];
    const float* th_w       = (const float*)d_in[14];
    const float* th_b       = (const float*)d_in[15];
    const float* al_w       = (const float*)d_in[16];
    const float* al_b       = (const float*)d_in[17];
    const float* be_w       = (const float*)d_in[18];
    const float* be_b       = (const float*)d_in[19];
    float* out = (float*)d_out;

    static int configured = 0;
    if (!configured) {
        cudaFuncSetAttribute(k_scan, cudaFuncAttributeMaxDynamicSharedMemorySize, SCAN_SMEM);
        cudaFuncSetAttribute(k_epi,  cudaFuncAttributeMaxDynamicSharedMemorySize, EPI_SMEM);
        configured = 1;
    }

    k_qtab<<<QN, 64>>>(q_embed_w, key_mem, sum_w, sum_b, al_w, al_b, be_w, be_b);
    k_vtab<<<QN * KN, DVN>>>(item_w, vp_w, vp_b, er_w, er_b, ad_w, ad_b);
    k_scan<<<BN, 512, SCAN_SMEM>>>(questions, responses, init_mem);
    k_epi<<<(BN * SN) / TILE_T, 256, EPI_SMEM>>>(questions, sum_w, th_w, th_b, out);
}

// round 6
// speedup vs baseline: 1.8436x; 1.2113x over previous
#include <cuda_runtime.h>
#include <math.h>

#define QN 1000
#define KN 5
#define MN 50
#define DKN 64
#define DVN 128
#define DSN 50
#define BN 128
#define SN 2048

typedef unsigned long long ull;

// ---------- f32x2 helpers ----------
__device__ __forceinline__ ull ffma2(ull a, ull b, ull c) {
    ull d;
    asm("fma.rn.f32x2 %0, %1, %2, %3;" : "=l"(d) : "l"(a), "l"(b), "l"(c));
    return d;
}
__device__ __forceinline__ ull fpack2(float lo, float hi) {
    ull r;
    asm("mov.b64 %0, {%1, %2};" : "=l"(r) : "f"(lo), "f"(hi));
    return r;
}
__device__ __forceinline__ float2 funpack2(ull v) {
    float2 f;
    asm("mov.b64 {%0, %1}, %2;" : "=f"(f.x), "=f"(f.y) : "l"(v));
    return f;
}

// ---------- scratch ----------
__device__ float g_attn[QN * MN];
__device__ float g_sq[QN * DSN];
__device__ float g_alphat[QN];
__device__ float g_betat[QN * (KN - 1)];
__device__ float g_erase[QN * KN * DVN];
__device__ float g_addt[QN * KN * DVN];
__device__ float g_reads[(size_t)BN * SN * DVN];

// ================= Kernel A: per-question tables =================
__global__ void k_qtab(const float* __restrict__ qe_w, const float* __restrict__ key_mem,
                       const float* __restrict__ sum_w, const float* __restrict__ sum_b,
                       const float* __restrict__ al_w, const float* __restrict__ al_b,
                       const float* __restrict__ be_w, const float* __restrict__ be_b) {
    int q = blockIdx.x, t = threadIdx.x;
    __shared__ float qe[DKN];
    __shared__ float sl[MN], se[MN];
    qe[t] = qe_w[q * DKN + t];
    __syncthreads();
    if (t < MN) {
        float acc = 0.f;
        #pragma unroll 8
        for (int k = 0; k < DKN; ++k) acc += qe[k] * key_mem[t * DKN + k];
        sl[t] = acc;
    }
    __syncthreads();
    if (t < MN) {
        float mx = -1e30f;
        for (int j = 0; j < MN; ++j) mx = fmaxf(mx, sl[j]);
        se[t] = expf(sl[t] - mx);
    }
    __syncthreads();
    if (t < MN) {
        float sm = 0.f;
        for (int j = 0; j < MN; ++j) sm += se[j];
        g_attn[q * MN + t] = se[t] / sm;
    }
    if (t < DSN) {
        float acc = sum_b[t];
        #pragma unroll 8
        for (int k = 0; k < DKN; ++k) acc += qe[k] * sum_w[(DVN + k) * DSN + t];
        g_sq[q * DSN + t] = acc;
    }
    if (t == 0) {
        float acc = al_b[0];
        for (int k = 0; k < DKN; ++k) acc += qe[k] * al_w[k];
        g_alphat[q] = fmaxf(acc, 0.f) + log1pf(expf(-fabsf(acc)));
    }
    if (t < KN - 1) {
        float acc = be_b[t];
        for (int k = 0; k < DKN; ++k) acc += qe[k] * be_w[k * (KN - 1) + t];
        g_betat[q * (KN - 1) + t] = acc;
    }
}

// ================= Kernel B: per-(q,r) erase/add tables =================
__global__ void k_vtab(const float* __restrict__ item_w,
                       const float* __restrict__ vp_w, const float* __restrict__ vp_b,
                       const float* __restrict__ er_w, const float* __restrict__ er_b,
                       const float* __restrict__ ad_w, const float* __restrict__ ad_b) {
    int c = blockIdx.x;
    int q = c / KN, r = c % KN;
    int t = threadIdx.x;
    __shared__ float item[DKN], rf[KN], ve[DVN];
    if (t < DKN) item[t] = item_w[q * DKN + t];
    if (t < KN)  rf[t] = fmaxf(1.f - fabsf((float)t - (float)r) * 0.25f, 0.f);
    __syncthreads();
    float acc = vp_b[t];
    #pragma unroll 8
    for (int k = 0; k < DKN; ++k) acc += item[k] * vp_w[k * DVN + t];
    #pragma unroll
    for (int j = 0; j < KN; ++j) acc += rf[j] * vp_w[(DKN + j) * DVN + t];
    ve[t] = acc;
    __syncthreads();
    float e = er_b[t], a = ad_b[t];
    #pragma unroll 8
    for (int k = 0; k < DVN; ++k) {
        float v = ve[k];
        e += v * er_w[k * DVN + t];
        a += v * ad_w[k * DVN + t];
    }
    g_erase[c * DVN + t] = 1.f / (1.f + expf(-e));
    g_addt[c * DVN + t]  = tanhf(a);
}

// ================= Kernel C: sequential scan (v6 = v2 + offset tables + attn prefetch, fp32 out) =================
// 128 CTAs, 256 threads = 8 warps (2/SMSP). Warp wid owns 8 v-pairs
// (vp = wid*8 + (lane&7)); mg = lane>>3: 4 m-groups of 13 (m 50..51 zero-pad).
// Per-thread state: 13 f32x2 memory pairs. Attention table in smem; next-step
// attention row prefetched into registers; per-step offsets precomputed.
#define ATT_PAD 52
#define SCAN_SMEM (QN * ATT_PAD * 4 + SN * 4 * 2)

__global__ void __launch_bounds__(256, 1)
k_scan(const int* __restrict__ questions, const int* __restrict__ responses,
       const float* __restrict__ init_mem) {
    extern __shared__ char smem_raw[];
    float* attn_sh = (float*)smem_raw;                       // QN*52 floats
    int*   aoff_sh = (int*)(smem_raw + QN * ATT_PAD * 4);    // q*52 per step
    int*   coff_sh = aoff_sh + SN;                           // (q*5+r)*128 per step

    int b = blockIdx.x, tid = threadIdx.x;
    int wid  = tid >> 5;
    int lane = tid & 31;
    int vsub = lane & 7;
    int mg   = lane >> 3;
    int vp   = wid * 8 + vsub;        // v-pair: v = 2vp, 2vp+1
    int mstart = mg * 13;

    for (int idx = tid; idx < QN * ATT_PAD; idx += 256) {
        int q = idx / ATT_PAD, m = idx - q * ATT_PAD;
        attn_sh[idx] = (m < MN) ? g_attn[q * MN + m] : 0.f;
    }
    for (int i = tid; i < SN; i += 256) {
        int q = questions[b * SN + i];
        int r = responses[b * SN + i];
        aoff_sh[i] = q * ATT_PAD;
        coff_sh[i] = (q * KN + r) * DVN;
    }

    ull mem[13];
    #pragma unroll
    for (int i = 0; i < 13; ++i) {
        int m = mstart + i;
        mem[i] = (m < MN) ? *(const ull*)(init_mem + m * DVN + 2 * vp) : 0ULL;
    }
    __syncthreads();

    // depth-2 erase/add prefetch pipeline
    int c0 = coff_sh[0];
    int c1 = coff_sh[1];
    ull e0  = *(const ull*)(g_erase + c0 + 2 * vp);
    ull ad0 = *(const ull*)(g_addt  + c0 + 2 * vp);
    ull e1  = *(const ull*)(g_erase + c1 + 2 * vp);
    ull ad1 = *(const ull*)(g_addt  + c1 + 2 * vp);

    // attention register prefetch: acur holds step-t row slice
    float acur[13];
    {
        int a0 = aoff_sh[0] + mstart;
        #pragma unroll
        for (int i = 0; i < 13; ++i) acur[i] = attn_sh[a0 + i];
    }

    float* outp = g_reads + (size_t)b * SN * DVN + 2 * vp;

    #pragma unroll 2
    for (int t = 0; t < SN; ++t) {
        ull e_cur = e0, ad_cur = ad0;
        e0 = e1; ad0 = ad1;
        int tp = (t + 2 < SN) ? t + 2 : SN - 1;
        int cp = coff_sh[tp];
        e1  = *(const ull*)(g_erase + cp + 2 * vp);
        ad1 = *(const ull*)(g_addt  + cp + 2 * vp);

        int anx = aoff_sh[(t + 1 < SN) ? t + 1 : SN - 1] + mstart;

        ull neg_e = e_cur ^ 0x8000000080000000ULL;
        ull r0 = 0ULL, r1 = 0ULL;
        #pragma unroll
        for (int i = 0; i < 13; ++i) {
            float a = acur[i];
            acur[i] = attn_sh[anx + i];              // prefetch next step's value
            ull ap = fpack2(a, a);
            ull tmp = ffma2(neg_e, mem[i], ad_cur);  // add - e*mem
            if (i & 1) r1 = ffma2(ap, mem[i], r1);
            else       r0 = ffma2(ap, mem[i], r0);
            mem[i] = ffma2(ap, tmp, mem[i]);         // mem += a*(add - e*mem)
        }
        float2 fa = funpack2(r0), fb = funpack2(r1);
        float rx = fa.x + fb.x, ry = fa.y + fb.y;
        rx += __shfl_xor_sync(0xffffffffu, rx, 8);
        ry += __shfl_xor_sync(0xffffffffu, ry, 8);
        rx += __shfl_xor_sync(0xffffffffu, rx, 16);
        ry += __shfl_xor_sync(0xffffffffu, ry, 16);
        if (mg == 0)
            *(float2*)(outp + (size_t)t * DVN) = make_float2(rx, ry);
    }
}

// ================= Kernel D: epilogue (v2 verbatim: 175us known-good) =================
#define TILE_T 128
#define R_STRIDE 132
#define W_STRIDE 26
#define EPI_SMEM (TILE_T * R_STRIDE * 4 + (DVN * W_STRIDE + 4) * 8)

__global__ void __launch_bounds__(256, 2)
k_epi(const int* __restrict__ questions,
      const float* __restrict__ sum_w,
      const float* __restrict__ th_w, const float* __restrict__ th_b,
      float* __restrict__ out) {
    extern __shared__ char smem_raw[];
    float* tileR = (float*)smem_raw;
    ull*   Wsu   = (ull*)(smem_raw + TILE_T * R_STRIDE * 4);
    float* Wsf   = (float*)Wsu;

    int tid = threadIdx.x;
    int t0 = blockIdx.x * TILE_T;

    // stage reads tile: coalesced float4
    for (int i = tid; i < TILE_T * (DVN / 4); i += 256) {
        int r = i >> 5, c4 = i & 31;
        float4 v = *(const float4*)(g_reads + (size_t)(t0 + r) * DVN + c4 * 4);
        *(float4*)(tileR + r * R_STRIDE + c4 * 4) = v;
    }
    // stage Ws (rows 0..127 of summary_w), zero-padded cols 50,51
    for (int i = tid; i < DVN * (2 * W_STRIDE); i += 256) {
        int v = i / (2 * W_STRIDE), j = i - v * (2 * W_STRIDE);
        Wsf[i] = (j < DSN) ? sum_w[v * DSN + j] : 0.f;
    }
    __syncthreads();

    int tg = tid >> 2;        // 0..63
    int jq = tid & 3;         // 0..3
    const float* rrow0 = tileR + tg * R_STRIDE;
    const float* rrow1 = tileR + (tg + 64) * R_STRIDE;
    const ull* wbase = Wsu + jq * 7;

    ull acc0[7], acc1[7];
    #pragma unroll
    for (int k = 0; k < 7; ++k) { acc0[k] = 0ULL; acc1[k] = 0ULL; }

    #pragma unroll 4
    for (int v = 0; v < DVN; ++v) {
        float rv0 = rrow0[v], rv1 = rrow1[v];
        ull rp0 = fpack2(rv0, rv0);
        ull rp1 = fpack2(rv1, rv1);
        const ull* w = wbase + v * W_STRIDE;
        #pragma unroll
        for (int k = 0; k < 7; ++k) {
            ull wv = w[k];
            acc0[k] = ffma2(rp0, wv, acc0[k]);
            acc1[k] = ffma2(rp1, wv, acc1[k]);
        }
    }

    float thb = th_b[0];
    const int N = BN * SN;

    #pragma unroll
    for (int i = 0; i < 2; ++i) {
        int task = t0 + tg + 64 * i;
        ull* acc = i ? acc1 : acc0;
        int qid = questions[task];
        float thp = 0.f;
        #pragma unroll
        for (int k = 0; k < 7; ++k) {
            int p = jq * 7 + k;
            if (p < 25) {
                float2 ac = funpack2(acc[k]);
                float2 sq2 = funpack2(*(const ull*)(g_sq + qid * DSN + 2 * p));
                float2 tw  = funpack2(*(const ull*)(th_w + 2 * p));
                float s0 = tanhf(ac.x + sq2.x);
                float s1 = tanhf(ac.y + sq2.y);
                thp += s0 * tw.x + s1 * tw.y;
            }
        }
        thp += __shfl_xor_sync(0xffffffffu, thp, 1);
        thp += __shfl_xor_sync(0xffffffffu, thp, 2);
        if (jq == 0) {
            float theta = tanhf(thp + thb);
            float alpha = g_alphat[qid];
            float inter = theta * alpha;
            float b0 = g_betat[qid * 4 + 0];
            float b1 = g_betat[qid * 4 + 1];
            float b2 = g_betat[qid * 4 + 2];
            float b3 = g_betat[qid * 4 + 3];
            float l0 = 0.f;
            float l1 = inter - b0;
            float l2 = l1 + inter - b1;
            float l3 = l2 + inter - b2;
            float l4 = l3 + inter - b3;
            float mx = fmaxf(fmaxf(fmaxf(l0, l1), fmaxf(l2, l3)), l4);
            float e0x = expf(l0 - mx), e1x = expf(l1 - mx), e2x = expf(l2 - mx);
            float e3x = expf(l3 - mx), e4x = expf(l4 - mx);
            float inv = 1.f / (e0x + e1x + e2x + e3x + e4x);

            out[task] = theta;
            out[N + task] = alpha;
            float* bo = out + 2 * N + (size_t)task * 4;
            bo[0] = b0; bo[1] = b1; bo[2] = b2; bo[3] = b3;
            float* lo = out + 6 * N + (size_t)task * 5;
            lo[0] = l0; lo[1] = l1; lo[2] = l2; lo[3] = l3; lo[4] = l4;
            float* po = out + 11 * N + (size_t)task * 5;
            po[0] = e0x * inv; po[1] = e1x * inv; po[2] = e2x * inv;
            po[3] = e3x * inv; po[4] = e4x * inv;
        }
    }
}

// ================= launch =================
extern "C" void kernel_launch(void* const* d_in, const int* in_sizes, int n_in,
                              void* d_out, int out_size) {
    const int*   questions  = (const int*)d_in[0];
    const int*   responses  = (const int*)d_in[1];
    const float* q_embed_w  = (const float*)d_in[2];
    const float* item_w     = (const float*)d_in[3];
    const float* vp_w       = (const float*)d_in[4];
    const float* vp_b       = (const float*)d_in[5];
    const float* key_mem    = (const float*)d_in[6];
    const float* init_mem   = (const float*)d_in[7];
    const float* er_w       = (const float*)d_in[8];
    const float* er_b       = (const float*)d_in[9];
    const float* ad_w       = (const float*)d_in[10];
    const float* ad_b       = (const float*)d_in[11];
    const float* sum_w      = (const float*)d_in[12];
    const float* sum_b      = (const float*)d_in[13];
    const float* th_w       = (const float*)d_in[14];
    const float* th_b       = (const float*)d_in[15];
    const float* al_w       = (const float*)d_in[16];
    const float* al_b       = (const float*)d_in[17];
    const float* be_w       = (const float*)d_in[18];
    const float* be_b       = (const float*)d_in[19];
    float* out = (float*)d_out;

    static int configured = 0;
    if (!configured) {
        cudaFuncSetAttribute(k_scan, cudaFuncAttributeMaxDynamicSharedMemorySize, SCAN_SMEM);
        cudaFuncSetAttribute(k_epi,  cudaFuncAttributeMaxDynamicSharedMemorySize, EPI_SMEM);
        configured = 1;
    }

    k_qtab<<<QN, 64>>>(q_embed_w, key_mem, sum_w, sum_b, al_w, al_b, be_w, be_b);
    k_vtab<<<QN * KN, DVN>>>(item_w, vp_w, vp_b, er_w, er_b, ad_w, ad_b);
    k_scan<<<BN, 256, SCAN_SMEM>>>(questions, responses, init_mem);
    k_epi<<<(BN * SN) / TILE_T, 256, EPI_SMEM>>>(questions, sum_w, th_w, th_b, out);
}